// round 9
// baseline (speedup 1.0000x reference)
#include <cuda_runtime.h>
#include <cuda_bf16.h>
#include <math.h>
#include <stdint.h>

// Problem constants
#define BATCH 8
#define LV    16384
#define LVH   8192
#define NNODE 32767
#define NINT  16383           // internal nodes per batch
#define DH    256
#define TOTAL_ROWS (BATCH * NNODE)   // 262136

// GEMM tiling
#define TBM 128
#define TBN 128
#define NSTAGE 3
#define STG_BYTES 32768       // Ah(8K) Al(8K) Bh(8K) Bl(8K)
#define SMEM_DYN (NSTAGE * STG_BYTES)

// ---------------- scratch (device globals) ----------------------------------
__device__ __nv_bfloat16 g_Wh[1024 * 256];  // [W_iou|W_f]^T hi  [out_col][k]
__device__ __nv_bfloat16 g_Wl[1024 * 256];
__device__ __nv_bfloat16 g_Uh[1024 * 256];  // [U_iou|U_f]^T hi
__device__ __nv_bfloat16 g_Ul[1024 * 256];
__device__ __nv_bfloat16 g_xh[(size_t)TOTAL_ROWS * 256];
__device__ __nv_bfloat16 g_xl[(size_t)TOTAL_ROWS * 256];
__device__ __nv_bfloat16 g_hh[(size_t)TOTAL_ROWS * 256];
__device__ __nv_bfloat16 g_hl[(size_t)TOTAL_ROWS * 256];
__device__ __nv_bfloat16 g_sh[(size_t)BATCH * LVH * 256];   // sibling h-sum hi
__device__ __nv_bfloat16 g_sl[(size_t)BATCH * LVH * 256];
__device__ float g_xproj[(size_t)TOTAL_ROWS * 1024];
__device__ float g_c[(size_t)TOTAL_ROWS * 256];
__device__ float g_Riou[(size_t)BATCH * LVH * 768];
__device__ float g_Rf[(size_t)BATCH * LV * 256];

__device__ __forceinline__ float sigm(float x) { return 1.0f / (1.0f + expf(-x)); }

// ---------------- PTX helpers ------------------------------------------------
__device__ __forceinline__ uint32_t smem_u32(const void* p) {
    uint32_t a;
    asm("{ .reg .u64 t; cvta.to.shared.u64 t, %1; cvt.u32.u64 %0, t; }" : "=r"(a) : "l"(p));
    return a;
}
__device__ __forceinline__ void ldsm4(uint32_t& r0, uint32_t& r1, uint32_t& r2, uint32_t& r3, uint32_t addr) {
    asm volatile("ldmatrix.sync.aligned.m8n8.x4.shared.b16 {%0,%1,%2,%3},[%4];"
                 : "=r"(r0), "=r"(r1), "=r"(r2), "=r"(r3) : "r"(addr));
}
__device__ __forceinline__ void mma16816(float* c, const uint32_t* a, uint32_t b0, uint32_t b1) {
    asm volatile("mma.sync.aligned.m16n8k16.row.col.f32.bf16.bf16.f32 "
                 "{%0,%1,%2,%3},{%4,%5,%6,%7},{%8,%9},{%0,%1,%2,%3};"
                 : "+f"(c[0]), "+f"(c[1]), "+f"(c[2]), "+f"(c[3])
                 : "r"(a[0]), "r"(a[1]), "r"(a[2]), "r"(a[3]), "r"(b0), "r"(b1));
}
__device__ __forceinline__ void cp16(uint32_t dst, const void* src, int srcsz) {
    asm volatile("cp.async.cg.shared.global [%0], [%1], 16, %2;" :: "r"(dst), "l"(src), "r"(srcsz) : "memory");
}
#define CP_COMMIT() asm volatile("cp.async.commit_group;" ::: "memory")
#define CP_WAIT(n)  asm volatile("cp.async.wait_group %0;" :: "n"(n) : "memory")

// chunk-swizzled smem offset inside one 128x32 bf16 matrix (64B rows, 4x16B chunks)
__device__ __forceinline__ uint32_t swz(int r, int c) {
    return (uint32_t)(r * 64 + ((c ^ ((r >> 1) & 3)) << 4));
}
// split fp32x4 -> bf16 hi/lo, store 4 each
__device__ __forceinline__ void split_store4(__nv_bfloat16* hi, __nv_bfloat16* lo, float4 v) {
    __nv_bfloat16 a = __float2bfloat16_rn(v.x), b = __float2bfloat16_rn(v.y),
                  c = __float2bfloat16_rn(v.z), e = __float2bfloat16_rn(v.w);
    *(__nv_bfloat162*)(hi)     = __nv_bfloat162(a, b);
    *(__nv_bfloat162*)(hi + 2) = __nv_bfloat162(c, e);
    *(__nv_bfloat162*)(lo)     = __nv_bfloat162(__float2bfloat16_rn(v.x - __bfloat162float(a)),
                                                __float2bfloat16_rn(v.y - __bfloat162float(b)));
    *(__nv_bfloat162*)(lo + 2) = __nv_bfloat162(__float2bfloat16_rn(v.z - __bfloat162float(c)),
                                                __float2bfloat16_rn(v.w - __bfloat162float(e)));
}
__device__ __forceinline__ float4 add4(float4 a, float4 b) {
    return make_float4(a.x + b.x, a.y + b.y, a.z + b.z, a.w + b.w);
}

// ---------------- weight packing: transpose + bf16 hi/lo split ---------------
__global__ void pack_weights(const float* __restrict__ W_iou, const float* __restrict__ W_f,
                             const float* __restrict__ U_iou, const float* __restrict__ U_f) {
    int idx = blockIdx.x * blockDim.x + threadIdx.x;
    if (idx >= 1024 * 256) return;
    int j = idx / 256, k = idx % 256;
    float wv = (j < 768) ? W_iou[k * 768 + j] : W_f[k * 256 + (j - 768)];
    float uv = (j < 768) ? U_iou[k * 768 + j] : U_f[k * 256 + (j - 768)];
    __nv_bfloat16 wh = __float2bfloat16_rn(wv);
    g_Wh[idx] = wh;
    g_Wl[idx] = __float2bfloat16_rn(wv - __bfloat162float(wh));
    __nv_bfloat16 uh = __float2bfloat16_rn(uv);
    g_Uh[idx] = uh;
    g_Ul[idx] = __float2bfloat16_rn(uv - __bfloat162float(uh));
}

// ---------------- x hi/lo split ---------------------------------------------
__global__ void split_x(const float* __restrict__ x) {
    size_t i = (size_t)blockIdx.x * blockDim.x + threadIdx.x;
    const size_t n4 = (size_t)TOTAL_ROWS * 256 / 4;
    if (i >= n4) return;
    float4 v = ((const float4*)x)[i];
    split_store4(g_xh + 4 * i, g_xl + 4 * i, v);
}

// ---------------- mma.sync GEMM (3-term bf16 split), mode-parameterized ------
// grid.x = 8 tiles: bx<6 -> iou cols (0..767), bx>=6 -> f cols (768..1023).
// is_input=1: A=x(all rows) for iou, x(internal rows) for f; C=g_xproj (ldc 1024)
// is_input=0: iou: A=g_s (level-n parents, M=8n)  -> C=g_Riou (ldc 768)
//             f  : A=g_h (level-2n children, M=16n) -> C=g_Rf (ldc 256)
__global__ __launch_bounds__(256, 1)
void gemm_mma(int is_input, int n)
{
    const int bx = blockIdx.x;
    const bool iou = bx < 6;

    const __nv_bfloat16 *Ahg, *Alg, *Bhg, *Blg;
    float* C;
    int M, rpb, row_off, ns, ldc, cns, bcol, ccol;
    if (is_input) {
        Bhg = g_Wh; Blg = g_Wl; C = g_xproj; ldc = 1024;
        Ahg = g_xh; Alg = g_xl;
        if (iou) { M = TOTAL_ROWS; rpb = M; row_off = 0; ns = 0; cns = 0; bcol = bx * 128; }
        else     { M = BATCH * NINT; rpb = NINT; row_off = 0; ns = NNODE; cns = NNODE; bcol = 768 + (bx - 6) * 128; }
        ccol = bcol;
    } else {
        Bhg = g_Uh; Blg = g_Ul;
        if (iou) { Ahg = g_sh; Alg = g_sl; M = 8 * n; rpb = n; row_off = 0; ns = LVH;
                   C = g_Riou; ldc = 768; cns = n; bcol = bx * 128; ccol = bcol; }
        else     { Ahg = g_hh; Alg = g_hl; M = 16 * n; rpb = 2 * n; row_off = 2 * n - 1; ns = NNODE;
                   C = g_Rf; ldc = 256; cns = 2 * n; bcol = 768 + (bx - 6) * 128; ccol = (bx - 6) * 128; }
    }

    const int row0 = blockIdx.y * TBM;
    if (row0 >= M) return;

    extern __shared__ char smem[];
    const uint32_t sb = smem_u32(smem);
    const int tid = threadIdx.x, wid = tid >> 5, lane = tid & 31;
    const int wm = wid >> 2, wn = wid & 3;

    // loader: thread t owns row lr = t>>1, chunks c2, c2+1
    const int lr = tid >> 1;
    const int c2 = (tid & 1) * 2;
    size_t aoff; int asz;
    {
        int m = row0 + lr;
        if (m < M) {
            int bb = m / rpb, loc = m - bb * rpb;
            aoff = ((size_t)bb * ns + (size_t)(row_off + loc)) * 256;
            asz = 16;
        } else { aoff = 0; asz = 0; }
    }
    const size_t boff = (size_t)(bcol + lr) * 256;
    const uint32_t s0 = swz(lr, c2), s1 = swz(lr, c2 + 1);

#define LOAD_CHUNK(kc, st) do {                                               \
        uint32_t bs = sb + (uint32_t)(st) * STG_BYTES;                        \
        int kg = (kc) * 32;                                                   \
        cp16(bs + s0,          Ahg + aoff + kg + c2 * 8,       asz);          \
        cp16(bs + s1,          Ahg + aoff + kg + c2 * 8 + 8,   asz);          \
        cp16(bs + 8192 + s0,   Alg + aoff + kg + c2 * 8,       asz);          \
        cp16(bs + 8192 + s1,   Alg + aoff + kg + c2 * 8 + 8,   asz);          \
        cp16(bs + 16384 + s0,  Bhg + boff + kg + c2 * 8,       16);           \
        cp16(bs + 16384 + s1,  Bhg + boff + kg + c2 * 8 + 8,   16);           \
        cp16(bs + 24576 + s0,  Blg + boff + kg + c2 * 8,       16);           \
        cp16(bs + 24576 + s1,  Blg + boff + kg + c2 * 8 + 8,   16);           \
        CP_COMMIT();                                                          \
    } while (0)

    float acc[4][4][4];
#pragma unroll
    for (int mt = 0; mt < 4; mt++)
#pragma unroll
        for (int nt = 0; nt < 4; nt++)
#pragma unroll
            for (int e = 0; e < 4; e++) acc[mt][nt][e] = 0.0f;

#define COMPUTE_CHUNK(st) do {                                                \
        uint32_t cb = sb + (uint32_t)(st) * STG_BYTES;                        \
        _Pragma("unroll")                                                     \
        for (int ks = 0; ks < 2; ks++) {                                      \
            uint32_t ah[4][4], al[4][4];                                      \
            int cch = ks * 2 + (lane >> 4);                                   \
            _Pragma("unroll")                                                 \
            for (int mt = 0; mt < 4; mt++) {                                  \
                int mr = wm * 64 + mt * 16 + (lane & 15);                     \
                uint32_t ad = cb + swz(mr, cch);                              \
                ldsm4(ah[mt][0], ah[mt][1], ah[mt][2], ah[mt][3], ad);        \
                ldsm4(al[mt][0], al[mt][1], al[mt][2], al[mt][3], ad + 8192); \
            }                                                                 \
            _Pragma("unroll")                                                 \
            for (int nt2 = 0; nt2 < 2; nt2++) {                               \
                int nr = wn * 32 + nt2 * 16 + (lane & 15);                    \
                uint32_t bd = cb + 16384 + swz(nr, cch);                      \
                uint32_t bh[4], bl[4];                                        \
                ldsm4(bh[0], bh[1], bh[2], bh[3], bd);                        \
                ldsm4(bl[0], bl[1], bl[2], bl[3], bd + 8192);                 \
                _Pragma("unroll")                                             \
                for (int mt = 0; mt < 4; mt++) {                              \
                    mma16816(acc[mt][nt2 * 2],     ah[mt], bh[0], bh[2]);     \
                    mma16816(acc[mt][nt2 * 2],     ah[mt], bl[0], bl[2]);     \
                    mma16816(acc[mt][nt2 * 2],     al[mt], bh[0], bh[2]);     \
                    mma16816(acc[mt][nt2 * 2 + 1], ah[mt], bh[1], bh[3]);     \
                    mma16816(acc[mt][nt2 * 2 + 1], ah[mt], bl[1], bl[3]);     \
                    mma16816(acc[mt][nt2 * 2 + 1], al[mt], bh[1], bh[3]);     \
                }                                                             \
            }                                                                 \
        }                                                                     \
    } while (0)

    LOAD_CHUNK(0, 0);
    LOAD_CHUNK(1, 1);
    LOAD_CHUNK(2, 2);

    int st_c = 0;
#pragma unroll 1
    for (int kc = 0; kc < 6; kc++) {
        CP_WAIT(2);
        __syncthreads();
        COMPUTE_CHUNK(st_c);
        if (kc < 5) {
            __syncthreads();
            LOAD_CHUNK(kc + 3, st_c);
        }
        st_c = (st_c == 2) ? 0 : st_c + 1;
    }
    CP_WAIT(1); __syncthreads();
    COMPUTE_CHUNK(st_c);
    st_c = (st_c == 2) ? 0 : st_c + 1;
    CP_WAIT(0); __syncthreads();
    COMPUTE_CHUNK(st_c);

    // epilogue (C row mapping: m -> bb*cns + loc)
#pragma unroll
    for (int mt = 0; mt < 4; mt++) {
        int r_lo = row0 + wm * 64 + mt * 16 + (lane >> 2);
        int r_hi = r_lo + 8;
#pragma unroll
        for (int nt = 0; nt < 4; nt++) {
            int cc = ccol + wn * 32 + nt * 8 + 2 * (lane & 3);
            if (r_lo < M) {
                int bb = r_lo / rpb, loc = r_lo - bb * rpb;
                size_t crow = (size_t)bb * cns + loc;
                *(float2*)(&C[crow * ldc + cc]) = make_float2(acc[mt][nt][0], acc[mt][nt][1]);
            }
            if (r_hi < M) {
                int bb = r_hi / rpb, loc = r_hi - bb * rpb;
                size_t crow = (size_t)bb * cns + loc;
                *(float2*)(&C[crow * ldc + cc]) = make_float2(acc[mt][nt][2], acc[mt][nt][3]);
            }
        }
    }
#undef LOAD_CHUNK
#undef COMPUTE_CHUNK
}

// ---------------- leaf pairs: gates + h-sum for parents ---------------------
__global__ void leaf_pair(const float* __restrict__ b_iou) {
    int gid = blockIdx.x * blockDim.x + threadIdx.x;
    const int total = BATCH * LVH * 64;
    if (gid >= total) return;
    int d = (gid & 63) << 2;
    int rest = gid >> 6;
    int t = rest & (LVH - 1);
    int bb = rest >> 13;

    float4 bi = *(const float4*)(b_iou + d);
    float4 bo = *(const float4*)(b_iou + 256 + d);
    float4 bu = *(const float4*)(b_iou + 512 + d);

    float4 hs = make_float4(0.f, 0.f, 0.f, 0.f);
#pragma unroll
    for (int s = 0; s < 2; s++) {
        int j = NINT + 2 * t + s;
        size_t xrow = ((size_t)bb * NNODE + j) * 1024;
        float4 i4 = add4(*(const float4*)(g_xproj + xrow + d), bi);
        float4 o4 = add4(*(const float4*)(g_xproj + xrow + 256 + d), bo);
        float4 u4 = add4(*(const float4*)(g_xproj + xrow + 512 + d), bu);
        float4 c4, h4;
        c4.x = sigm(i4.x) * tanhf(u4.x); h4.x = sigm(o4.x) * tanhf(c4.x);
        c4.y = sigm(i4.y) * tanhf(u4.y); h4.y = sigm(o4.y) * tanhf(c4.y);
        c4.z = sigm(i4.z) * tanhf(u4.z); h4.z = sigm(o4.z) * tanhf(c4.z);
        c4.w = sigm(i4.w) * tanhf(u4.w); h4.w = sigm(o4.w) * tanhf(c4.w);
        size_t hrow = ((size_t)bb * NNODE + j) * 256 + d;
        *(float4*)(g_c + hrow) = c4;
        split_store4(g_hh + hrow, g_hl + hrow, h4);
        hs = add4(hs, h4);
    }
    size_t srow = ((size_t)bb * LVH + t) * 256 + d;
    split_store4(g_sh + srow, g_sl + srow, hs);
}

// ---------------- internal-level combine (pairs) -----------------------------
__global__ void combine_pair(const float* __restrict__ b_iou, const float* __restrict__ b_f, int n) {
    int gid = blockIdx.x * blockDim.x + threadIdx.x;
    const int half = n >> 1;
    const int total = BATCH * half * 64;
    if (gid >= total) return;
    int d = (gid & 63) << 2;
    int rest = gid >> 6;
    int t = rest % half;
    int bb = rest / half;

    float4 bi = *(const float4*)(b_iou + d);
    float4 bo = *(const float4*)(b_iou + 256 + d);
    float4 bu = *(const float4*)(b_iou + 512 + d);
    float4 bf = *(const float4*)(b_f + d);

    float4 hs = make_float4(0.f, 0.f, 0.f, 0.f);
#pragma unroll
    for (int s = 0; s < 2; s++) {
        int k = 2 * t + s;
        int j = n - 1 + k;
        size_t xrow = ((size_t)bb * NNODE + j) * 1024;
        size_t rrow = ((size_t)bb * n + k) * 768;
        float4 i4 = add4(add4(*(const float4*)(g_xproj + xrow + d),       *(const float4*)(g_Riou + rrow + d)),       bi);
        float4 o4 = add4(add4(*(const float4*)(g_xproj + xrow + 256 + d), *(const float4*)(g_Riou + rrow + 256 + d)), bo);
        float4 u4 = add4(add4(*(const float4*)(g_xproj + xrow + 512 + d), *(const float4*)(g_Riou + rrow + 512 + d)), bu);
        float4 fx = add4(*(const float4*)(g_xproj + xrow + 768 + d), bf);
        size_t rfrow = ((size_t)bb * 2 * n + 2 * k) * 256 + d;
        float4 f0 = *(const float4*)(g_Rf + rfrow);
        float4 f1 = *(const float4*)(g_Rf + rfrow + 256);
        size_t crow = ((size_t)bb * NNODE + 2 * j + 1) * 256 + d;
        float4 c0 = *(const float4*)(g_c + crow);
        float4 c1 = *(const float4*)(g_c + crow + 256);
        float4 c4, h4;
        c4.x = sigm(i4.x) * tanhf(u4.x) + sigm(fx.x + f0.x) * c0.x + sigm(fx.x + f1.x) * c1.x;
        c4.y = sigm(i4.y) * tanhf(u4.y) + sigm(fx.y + f0.y) * c0.y + sigm(fx.y + f1.y) * c1.y;
        c4.z = sigm(i4.z) * tanhf(u4.z) + sigm(fx.z + f0.z) * c0.z + sigm(fx.z + f1.z) * c1.z;
        c4.w = sigm(i4.w) * tanhf(u4.w) + sigm(fx.w + f0.w) * c0.w + sigm(fx.w + f1.w) * c1.w;
        h4.x = sigm(o4.x) * tanhf(c4.x);
        h4.y = sigm(o4.y) * tanhf(c4.y);
        h4.z = sigm(o4.z) * tanhf(c4.z);
        h4.w = sigm(o4.w) * tanhf(c4.w);
        size_t hrow = ((size_t)bb * NNODE + j) * 256 + d;
        *(float4*)(g_c + hrow) = c4;
        split_store4(g_hh + hrow, g_hl + hrow, h4);
        hs = add4(hs, h4);
    }
    size_t srow = ((size_t)bb * LVH + t) * 256 + d;
    split_store4(g_sh + srow, g_sl + srow, hs);
}

// ---------------- fused tail: levels n=8,4,2,1 + output ----------------------
__global__ void tail_k(const float* __restrict__ b_iou, const float* __restrict__ b_f,
                       const float* __restrict__ U_iou, const float* __restrict__ U_f,
                       float* __restrict__ out) {
    __shared__ float hc[16][256], cc[16][256], hn[8][256], cn[8][256];
    int bb = blockIdx.x;
    int d = threadIdx.x;

    // load level-16 children (nodes j=15..30)
#pragma unroll
    for (int kk = 0; kk < 16; kk++) {
        size_t r = ((size_t)bb * NNODE + 15 + kk) * 256 + d;
        hc[kk][d] = __bfloat162float(g_hh[r]) + __bfloat162float(g_hl[r]);
        cc[kk][d] = g_c[r];
    }
    __syncthreads();

    float bi = b_iou[d], bo = b_iou[256 + d], bu = b_iou[512 + d], bfv = b_f[d];

    for (int n = 8; n >= 1; n >>= 1) {
        for (int k = 0; k < n; k++) {
            float ai = 0.f, ao = 0.f, au = 0.f, af0 = 0.f, af1 = 0.f;
#pragma unroll 4
            for (int kk = 0; kk < 256; kk++) {
                float h0 = hc[2 * k][kk], h1 = hc[2 * k + 1][kk];
                float hsv = h0 + h1;
                float wi = U_iou[kk * 768 + d];
                float wo = U_iou[kk * 768 + 256 + d];
                float wu = U_iou[kk * 768 + 512 + d];
                float wf = U_f[kk * 256 + d];
                ai = fmaf(hsv, wi, ai);
                ao = fmaf(hsv, wo, ao);
                au = fmaf(hsv, wu, au);
                af0 = fmaf(h0, wf, af0);
                af1 = fmaf(h1, wf, af1);
            }
            int j = n - 1 + k;
            size_t xrow = ((size_t)bb * NNODE + j) * 1024;
            float iv = g_xproj[xrow + d] + bi + ai;
            float ov = g_xproj[xrow + 256 + d] + bo + ao;
            float uv = g_xproj[xrow + 512 + d] + bu + au;
            float fx = g_xproj[xrow + 768 + d] + bfv;
            float cv = sigm(iv) * tanhf(uv) + sigm(fx + af0) * cc[2 * k][d] + sigm(fx + af1) * cc[2 * k + 1][d];
            float hv = sigm(ov) * tanhf(cv);
            hn[k][d] = hv;
            cn[k][d] = cv;
            if (n == 1) {
                out[bb * 512 + d] = hv;
                out[bb * 512 + 256 + d] = cv;
            }
        }
        __syncthreads();
        for (int k = 0; k < n; k++) { hc[k][d] = hn[k][d]; cc[k][d] = cn[k][d]; }
        __syncthreads();
    }
}

// ---------------- launch ----------------------------------------------------
extern "C" void kernel_launch(void* const* d_in, const int* in_sizes, int n_in,
                              void* d_out, int out_size) {
    const float* x     = (const float*)d_in[0];
    const float* W_iou = (const float*)d_in[1];
    const float* b_iou = (const float*)d_in[2];
    const float* U_iou = (const float*)d_in[3];
    const float* W_f   = (const float*)d_in[4];
    const float* b_f   = (const float*)d_in[5];
    const float* U_f   = (const float*)d_in[6];
    float* out = (float*)d_out;

    cudaFuncSetAttribute(gemm_mma, cudaFuncAttributeMaxDynamicSharedMemorySize, SMEM_DYN);

    pack_weights<<<(1024 * 256 + 255) / 256, 256>>>(W_iou, W_f, U_iou, U_f);
    {
        size_t n4 = (size_t)TOTAL_ROWS * 256 / 4;
        split_x<<<(unsigned)((n4 + 255) / 256), 256>>>(x);
    }

    // input projection: iou cols for all rows, f cols for internal rows
    {
        dim3 grid(8, (TOTAL_ROWS + TBM - 1) / TBM);
        gemm_mma<<<grid, 256, SMEM_DYN>>>(1, 0);
    }

    // leaves (pairs, also writes h-sum for n=8192 parents)
    leaf_pair<<<BATCH * LVH * 64 / 256, 256>>>(b_iou);

    // levels 8192 .. 16 (generic tensor-core path)
    for (int n = LVH; n >= 16; n >>= 1) {
        dim3 grid(8, (16 * n + TBM - 1) / TBM);
        gemm_mma<<<grid, 256, SMEM_DYN>>>(0, n);
        int total = BATCH * (n >> 1) * 64;
        combine_pair<<<(total + 255) / 256, 256>>>(b_iou, b_f, n);
    }

    // levels 8,4,2,1 fused + output
    tail_k<<<BATCH, 256>>>(b_iou, b_f, U_iou, U_f, out);
}